// round 2
// baseline (speedup 1.0000x reference)
#include <cuda_runtime.h>

#define NPTS  16384      // N*P
#define KNB   16         // K neighbors
#define CIN   128
#define CMID  64
#define COUT  256
#define CCAT  192
#define CDIM  384        // C_CAT * DM
#define KK    256        // K*K
#define SW    260        // padded smem stride (multiple of 4 -> float4-aligned)

// Scratch (allocation-free rule: __device__ globals)
__device__ float g_lift[NPTS * KNB * CMID];   // 16.7M floats, fts_lifted
__device__ float g_X[NPTS * KK];              // 4.2M floats, X matrices
__device__ float g_stats[2 * COUT];           // BN sum / sumsq

// ---------------------------------------------------------------------------
__global__ void k_zero_stats() { g_stats[threadIdx.x] = 0.f; }

// ---------------------------------------------------------------------------
// K1: pts_local -> h=relu(@d1) -> fts_lifted=relu(@d2)  (rows = NPTS*KNB)
// 64 rows per block, d1/d2 weights in SMEM, 4x4 register tiles for d2 GEMM.
__global__ __launch_bounds__(256) void k_lift(
    const float* __restrict__ pts, const float* __restrict__ rep,
    const float* __restrict__ w1, const float* __restrict__ b1,
    const float* __restrict__ w2, const float* __restrict__ b2)
{
    __shared__ float s_w1[3 * 64], s_b1[64], s_w2[64 * 64], s_b2[64];
    __shared__ float s_ploc[64 * 3];
    __shared__ float s_h[64 * 65];   // padded stride 65 (scalar access only)

    int tid = threadIdx.x;
    if (tid < 192) s_w1[tid] = w1[tid];
    if (tid < 64) { s_b1[tid] = b1[tid]; s_b2[tid] = b2[tid]; }
    for (int i = tid; i < 4096; i += 256) s_w2[i] = w2[i];

    int row0 = blockIdx.x * 64;
    if (tid < 192) {
        int lr = tid / 3, d = tid - lr * 3;
        int gr = row0 + lr;
        s_ploc[tid] = pts[gr * 3 + d] - rep[(gr >> 4) * 3 + d];
    }
    __syncthreads();

    #pragma unroll
    for (int it = 0; it < 16; it++) {
        int idx = tid + it * 256;
        int lr = idx >> 6, m = idx & 63;
        float a = s_b1[m];
        a = fmaf(s_ploc[lr * 3 + 0], s_w1[m],        a);
        a = fmaf(s_ploc[lr * 3 + 1], s_w1[64 + m],   a);
        a = fmaf(s_ploc[lr * 3 + 2], s_w1[128 + m],  a);
        s_h[lr * 65 + m] = fmaxf(a, 0.f);
    }
    __syncthreads();

    int rg = tid >> 4, cg = tid & 15;
    int r0 = rg * 4, c0 = cg * 4;
    float acc[4][4];
    #pragma unroll
    for (int i = 0; i < 4; i++)
        #pragma unroll
        for (int jj = 0; jj < 4; jj++) acc[i][jj] = s_b2[c0 + jj];

    #pragma unroll 8
    for (int j = 0; j < 64; j++) {
        float4 w = *(const float4*)&s_w2[j * 64 + c0];   // 64-stride: aligned
        #pragma unroll
        for (int i = 0; i < 4; i++) {
            float h = s_h[(r0 + i) * 65 + j];
            acc[i][0] = fmaf(h, w.x, acc[i][0]);
            acc[i][1] = fmaf(h, w.y, acc[i][1]);
            acc[i][2] = fmaf(h, w.z, acc[i][2]);
            acc[i][3] = fmaf(h, w.w, acc[i][3]);
        }
    }
    #pragma unroll
    for (int i = 0; i < 4; i++) {
        int gr = row0 + r0 + i;
        float4 v;
        v.x = fmaxf(acc[i][0], 0.f);
        v.y = fmaxf(acc[i][1], 0.f);
        v.z = fmaxf(acc[i][2], 0.f);
        v.w = fmaxf(acc[i][3], 0.f);
        *(float4*)&g_lift[gr * 64 + c0] = v;
    }
}

// ---------------------------------------------------------------------------
// K2: X-transform path: conv(48->256) -> relu -> x1(256) -> relu -> x2(256).
// 16 points per block; weight tiles staged (transposed, padded) in SMEM.
// Thread tile: 2 points x 8 outputs.
__global__ __launch_bounds__(256) void k_xtrans(
    const float* __restrict__ pts, const float* __restrict__ rep,
    const float* __restrict__ cvw, const float* __restrict__ cvb,
    const float* __restrict__ x1w, const float* __restrict__ x1b,
    const float* __restrict__ x2w, const float* __restrict__ x2b)
{
    extern __shared__ float sm[];
    float* s_ploc = sm;                 // 16*48 = 768   (layout [p][i], i=d*16+k)
    float* s_xa   = sm + 768;           // 16*256 = 4096
    float* s_xb   = s_xa + 4096;        // 4096
    float* s_w    = s_xb + 4096;        // 48*260 = 12480

    int tid = threadIdx.x;
    int p0 = blockIdx.x * 16;

    for (int idx = tid; idx < 768; idx += 256) {
        int p = idx / 48, i = idx - p * 48;
        int d = i >> 4, k = i & 15;
        int gp = p0 + p;
        s_ploc[idx] = pts[((gp << 4) + k) * 3 + d] - rep[gp * 3 + d];
    }
    // transpose conv weights: s_w[i][o] = cv_w[o][i]   (i = d*16+k)
    for (int idx = tid; idx < 12288; idx += 256) {
        int o = idx / 48, i = idx - o * 48;
        s_w[i * SW + o] = cvw[idx];
    }
    __syncthreads();

    int prow = tid >> 5, oc = tid & 31;
    int pa = prow * 2;
    int o0 = oc * 8;
    float acc[2][8];

    // ---- conv stage ----
    #pragma unroll
    for (int oo = 0; oo < 8; oo++) { float b = cvb[o0 + oo]; acc[0][oo] = b; acc[1][oo] = b; }
    #pragma unroll 4
    for (int i = 0; i < 48; i++) {
        float va = s_ploc[pa * 48 + i], vb = s_ploc[(pa + 1) * 48 + i];
        float4 w0 = *(const float4*)&s_w[i * SW + o0];
        float4 w1 = *(const float4*)&s_w[i * SW + o0 + 4];
        acc[0][0] = fmaf(va, w0.x, acc[0][0]); acc[0][1] = fmaf(va, w0.y, acc[0][1]);
        acc[0][2] = fmaf(va, w0.z, acc[0][2]); acc[0][3] = fmaf(va, w0.w, acc[0][3]);
        acc[0][4] = fmaf(va, w1.x, acc[0][4]); acc[0][5] = fmaf(va, w1.y, acc[0][5]);
        acc[0][6] = fmaf(va, w1.z, acc[0][6]); acc[0][7] = fmaf(va, w1.w, acc[0][7]);
        acc[1][0] = fmaf(vb, w0.x, acc[1][0]); acc[1][1] = fmaf(vb, w0.y, acc[1][1]);
        acc[1][2] = fmaf(vb, w0.z, acc[1][2]); acc[1][3] = fmaf(vb, w0.w, acc[1][3]);
        acc[1][4] = fmaf(vb, w1.x, acc[1][4]); acc[1][5] = fmaf(vb, w1.y, acc[1][5]);
        acc[1][6] = fmaf(vb, w1.z, acc[1][6]); acc[1][7] = fmaf(vb, w1.w, acc[1][7]);
    }
    #pragma unroll
    for (int pi = 0; pi < 2; pi++) {
        float4 v0, v1;
        v0.x = fmaxf(acc[pi][0], 0.f); v0.y = fmaxf(acc[pi][1], 0.f);
        v0.z = fmaxf(acc[pi][2], 0.f); v0.w = fmaxf(acc[pi][3], 0.f);
        v1.x = fmaxf(acc[pi][4], 0.f); v1.y = fmaxf(acc[pi][5], 0.f);
        v1.z = fmaxf(acc[pi][6], 0.f); v1.w = fmaxf(acc[pi][7], 0.f);
        *(float4*)&s_xa[(pa + pi) * 256 + o0] = v0;
        *(float4*)&s_xa[(pa + pi) * 256 + o0 + 4] = v1;
    }

    // ---- x1 stage (relu) ----
    #pragma unroll
    for (int oo = 0; oo < 8; oo++) { float b = x1b[o0 + oo]; acc[0][oo] = b; acc[1][oo] = b; }
    for (int jt = 0; jt < 256; jt += 32) {
        __syncthreads();
        for (int idx = tid; idx < 8192; idx += 256) {
            int jj = idx >> 8, o = idx & 255;
            s_w[jj * SW + o] = x1w[(jt + jj) * 256 + o];
        }
        __syncthreads();
        #pragma unroll 4
        for (int jj = 0; jj < 32; jj++) {
            float va = s_xa[pa * 256 + jt + jj], vb = s_xa[(pa + 1) * 256 + jt + jj];
            float4 w0 = *(const float4*)&s_w[jj * SW + o0];
            float4 w1 = *(const float4*)&s_w[jj * SW + o0 + 4];
            acc[0][0] = fmaf(va, w0.x, acc[0][0]); acc[0][1] = fmaf(va, w0.y, acc[0][1]);
            acc[0][2] = fmaf(va, w0.z, acc[0][2]); acc[0][3] = fmaf(va, w0.w, acc[0][3]);
            acc[0][4] = fmaf(va, w1.x, acc[0][4]); acc[0][5] = fmaf(va, w1.y, acc[0][5]);
            acc[0][6] = fmaf(va, w1.z, acc[0][6]); acc[0][7] = fmaf(va, w1.w, acc[0][7]);
            acc[1][0] = fmaf(vb, w0.x, acc[1][0]); acc[1][1] = fmaf(vb, w0.y, acc[1][1]);
            acc[1][2] = fmaf(vb, w0.z, acc[1][2]); acc[1][3] = fmaf(vb, w0.w, acc[1][3]);
            acc[1][4] = fmaf(vb, w1.x, acc[1][4]); acc[1][5] = fmaf(vb, w1.y, acc[1][5]);
            acc[1][6] = fmaf(vb, w1.z, acc[1][6]); acc[1][7] = fmaf(vb, w1.w, acc[1][7]);
        }
    }
    #pragma unroll
    for (int pi = 0; pi < 2; pi++) {
        float4 v0, v1;
        v0.x = fmaxf(acc[pi][0], 0.f); v0.y = fmaxf(acc[pi][1], 0.f);
        v0.z = fmaxf(acc[pi][2], 0.f); v0.w = fmaxf(acc[pi][3], 0.f);
        v1.x = fmaxf(acc[pi][4], 0.f); v1.y = fmaxf(acc[pi][5], 0.f);
        v1.z = fmaxf(acc[pi][6], 0.f); v1.w = fmaxf(acc[pi][7], 0.f);
        *(float4*)&s_xb[(pa + pi) * 256 + o0] = v0;
        *(float4*)&s_xb[(pa + pi) * 256 + o0 + 4] = v1;
    }

    // ---- x2 stage (no relu) ----
    #pragma unroll
    for (int oo = 0; oo < 8; oo++) { float b = x2b[o0 + oo]; acc[0][oo] = b; acc[1][oo] = b; }
    for (int jt = 0; jt < 256; jt += 32) {
        __syncthreads();
        for (int idx = tid; idx < 8192; idx += 256) {
            int jj = idx >> 8, o = idx & 255;
            s_w[jj * SW + o] = x2w[(jt + jj) * 256 + o];
        }
        __syncthreads();
        #pragma unroll 4
        for (int jj = 0; jj < 32; jj++) {
            float va = s_xb[pa * 256 + jt + jj], vb = s_xb[(pa + 1) * 256 + jt + jj];
            float4 w0 = *(const float4*)&s_w[jj * SW + o0];
            float4 w1 = *(const float4*)&s_w[jj * SW + o0 + 4];
            acc[0][0] = fmaf(va, w0.x, acc[0][0]); acc[0][1] = fmaf(va, w0.y, acc[0][1]);
            acc[0][2] = fmaf(va, w0.z, acc[0][2]); acc[0][3] = fmaf(va, w0.w, acc[0][3]);
            acc[0][4] = fmaf(va, w1.x, acc[0][4]); acc[0][5] = fmaf(va, w1.y, acc[0][5]);
            acc[0][6] = fmaf(va, w1.z, acc[0][6]); acc[0][7] = fmaf(va, w1.w, acc[0][7]);
            acc[1][0] = fmaf(vb, w0.x, acc[1][0]); acc[1][1] = fmaf(vb, w0.y, acc[1][1]);
            acc[1][2] = fmaf(vb, w0.z, acc[1][2]); acc[1][3] = fmaf(vb, w0.w, acc[1][3]);
            acc[1][4] = fmaf(vb, w1.x, acc[1][4]); acc[1][5] = fmaf(vb, w1.y, acc[1][5]);
            acc[1][6] = fmaf(vb, w1.z, acc[1][6]); acc[1][7] = fmaf(vb, w1.w, acc[1][7]);
        }
    }
    #pragma unroll
    for (int pi = 0; pi < 2; pi++) {
        int gp = p0 + pa + pi;
        float4 v0 = { acc[pi][0], acc[pi][1], acc[pi][2], acc[pi][3] };
        float4 v1 = { acc[pi][4], acc[pi][5], acc[pi][6], acc[pi][7] };
        *(float4*)&g_X[gp * 256 + o0] = v0;
        *(float4*)&g_X[gp * 256 + o0 + 4] = v1;
    }
}

// ---------------------------------------------------------------------------
// K3: per point: fts_X = X @ cat ; depthwise ; pointwise ; relu ; BN stats.
// 16 points per block; pw_w tiled transposed in SMEM; thread tile 2p x 8o.
__global__ __launch_bounds__(256) void k_combine(
    const float* __restrict__ fts, const float* __restrict__ dww,
    const float* __restrict__ dwb, const float* __restrict__ pww,
    float* __restrict__ out)
{
    extern __shared__ float sm[];
    float* s_X   = sm;               // 4096
    float* s_cat = s_X + 4096;       // 3072
    float* s_fx  = s_cat + 3072;     // 3072
    float* s_dw  = s_fx + 3072;      // 6144
    float* s_pw  = s_dw + 6144;      // 32*260 = 8320
    float* s_sum = s_pw + 8320;      // 256
    float* s_ssq = s_sum + 256;      // 256

    int tid = threadIdx.x;
    int p0 = blockIdx.x * 16;

    for (int idx = tid; idx < 4096; idx += 256) s_X[idx] = g_X[p0 * 256 + idx];
    s_sum[tid] = 0.f; s_ssq[tid] = 0.f;

    for (int p = 0; p < 16; p++) {
        int gp = p0 + p;
        __syncthreads();
        // build fts_cat = [lifted(64) | fts(128)]
        for (int idx = tid; idx < 3072; idx += 256) {
            int k = idx / 192, c = idx - k * 192;
            s_cat[idx] = (c < 64) ? g_lift[(gp * 16 + k) * 64 + c]
                                  : fts[(gp * 16 + k) * 128 + (c - 64)];
        }
        __syncthreads();
        // fts_X[k][c] = sum_j X[k][j] * cat[j][c]
        for (int idx = tid; idx < 3072; idx += 256) {
            int k = idx / 192, c = idx - k * 192;
            const float* Xr = &s_X[p * 256 + k * 16];
            float a = 0.f;
            #pragma unroll
            for (int j = 0; j < 16; j++) a = fmaf(Xr[j], s_cat[j * 192 + c], a);
            s_fx[idx] = a;
        }
        __syncthreads();
        // depthwise: dw[c*2+m] = b + sum_k fx[k][c] * dww[(c*2+m)*16+k]
        for (int idx = tid; idx < 384; idx += 256) {
            int c = idx >> 1;
            float a = dwb[idx];
            #pragma unroll
            for (int k = 0; k < 16; k++)
                a = fmaf(s_fx[k * 192 + c], dww[idx * 16 + k], a);
            s_dw[p * 384 + idx] = a;
        }
    }

    // pointwise GEMM: out[p][o] = sum_j dw[p][j] * pw_w[o][j]
    int prow = tid >> 5, oc = tid & 31;
    int pa = prow * 2, o0 = oc * 8;
    float acc[2][8];
    #pragma unroll
    for (int oo = 0; oo < 8; oo++) { acc[0][oo] = 0.f; acc[1][oo] = 0.f; }

    for (int jt = 0; jt < 384; jt += 32) {
        __syncthreads();
        for (int idx = tid; idx < 8192; idx += 256) {
            int o = idx >> 5, jj = idx & 31;
            s_pw[jj * SW + o] = pww[o * 384 + jt + jj];
        }
        __syncthreads();
        #pragma unroll 4
        for (int jj = 0; jj < 32; jj++) {
            float da = s_dw[pa * 384 + jt + jj], db = s_dw[(pa + 1) * 384 + jt + jj];
            float4 w0 = *(const float4*)&s_pw[jj * SW + o0];
            float4 w1 = *(const float4*)&s_pw[jj * SW + o0 + 4];
            acc[0][0] = fmaf(da, w0.x, acc[0][0]); acc[0][1] = fmaf(da, w0.y, acc[0][1]);
            acc[0][2] = fmaf(da, w0.z, acc[0][2]); acc[0][3] = fmaf(da, w0.w, acc[0][3]);
            acc[0][4] = fmaf(da, w1.x, acc[0][4]); acc[0][5] = fmaf(da, w1.y, acc[0][5]);
            acc[0][6] = fmaf(da, w1.z, acc[0][6]); acc[0][7] = fmaf(da, w1.w, acc[0][7]);
            acc[1][0] = fmaf(db, w0.x, acc[1][0]); acc[1][1] = fmaf(db, w0.y, acc[1][1]);
            acc[1][2] = fmaf(db, w0.z, acc[1][2]); acc[1][3] = fmaf(db, w0.w, acc[1][3]);
            acc[1][4] = fmaf(db, w1.x, acc[1][4]); acc[1][5] = fmaf(db, w1.y, acc[1][5]);
            acc[1][6] = fmaf(db, w1.z, acc[1][6]); acc[1][7] = fmaf(db, w1.w, acc[1][7]);
        }
    }

    // relu, store, local BN stats
    float vs[2][8];
    #pragma unroll
    for (int pi = 0; pi < 2; pi++) {
        int gp = p0 + pa + pi;
        #pragma unroll
        for (int oo = 0; oo < 8; oo++) vs[pi][oo] = fmaxf(acc[pi][oo], 0.f);
        float4 v0 = { vs[pi][0], vs[pi][1], vs[pi][2], vs[pi][3] };
        float4 v1 = { vs[pi][4], vs[pi][5], vs[pi][6], vs[pi][7] };
        *(float4*)&out[gp * 256 + o0] = v0;
        *(float4*)&out[gp * 256 + o0 + 4] = v1;
    }
    #pragma unroll
    for (int oo = 0; oo < 8; oo++) {
        float sv = vs[0][oo] + vs[1][oo];
        float sq = vs[0][oo] * vs[0][oo] + vs[1][oo] * vs[1][oo];
        atomicAdd(&s_sum[o0 + oo], sv);
        atomicAdd(&s_ssq[o0 + oo], sq);
    }
    __syncthreads();
    atomicAdd(&g_stats[tid],        s_sum[tid]);
    atomicAdd(&g_stats[COUT + tid], s_ssq[tid]);
}

// ---------------------------------------------------------------------------
// K4: BatchNorm normalize in place.
__global__ __launch_bounds__(256) void k_bn(
    float* __restrict__ out, const float* __restrict__ g, const float* __restrict__ b)
{
    int idx = blockIdx.x * 256 + threadIdx.x;
    int o = idx & 255;
    float mean = g_stats[o] * (1.0f / 16384.0f);
    float var  = g_stats[COUT + o] * (1.0f / 16384.0f) - mean * mean;
    float sc = rsqrtf(var + 1e-5f) * g[o];
    out[idx] = (out[idx] - mean) * sc + b[o];
}

// ---------------------------------------------------------------------------
extern "C" void kernel_launch(void* const* d_in, const int* in_sizes, int n_in,
                              void* d_out, int out_size)
{
    const float* rep = (const float*)d_in[0];
    const float* pts = (const float*)d_in[1];
    const float* fts = (const float*)d_in[2];
    const float* d1w = (const float*)d_in[3];
    const float* d1b = (const float*)d_in[4];
    const float* d2w = (const float*)d_in[5];
    const float* d2b = (const float*)d_in[6];
    const float* cvw = (const float*)d_in[7];
    const float* cvb = (const float*)d_in[8];
    const float* x1w = (const float*)d_in[9];
    const float* x1b = (const float*)d_in[10];
    const float* x2w = (const float*)d_in[11];
    const float* x2b = (const float*)d_in[12];
    const float* dww = (const float*)d_in[13];
    const float* dwb = (const float*)d_in[14];
    const float* pww = (const float*)d_in[15];
    const float* bng = (const float*)d_in[16];
    const float* bnb = (const float*)d_in[17];
    float* out = (float*)d_out;

    const int SM2 = 21440 * 4;   // k_xtrans dynamic smem bytes (85760)
    const int SM3 = 25216 * 4;   // k_combine dynamic smem bytes (100864)
    static int attr_done = 0;
    if (!attr_done) {
        cudaFuncSetAttribute(k_xtrans,  cudaFuncAttributeMaxDynamicSharedMemorySize, SM2);
        cudaFuncSetAttribute(k_combine, cudaFuncAttributeMaxDynamicSharedMemorySize, SM3);
        attr_done = 1;
    }

    k_zero_stats<<<1, 512>>>();
    k_lift<<<4096, 256>>>(pts, rep, d1w, d1b, d2w, d2b);
    k_xtrans<<<1024, 256, SM2>>>(pts, rep, cvw, cvb, x1w, x1b, x2w, x2b);
    k_combine<<<1024, 256, SM3>>>(fts, dww, dwb, pww, out);
    k_bn<<<16384, 256>>>(out, bng, bnb);
}

// round 4
// speedup vs baseline: 2.3241x; 2.3241x over previous
#include <cuda_runtime.h>

#define NPTS  16384
#define KNB   16
#define CIN   128
#define CMID  64
#define COUT  256
#define CCAT  192
#define CDIM  384
#define SA    68          // sA row pad
#define SB    260         // sB row pad

// Scratch (__device__ globals: allocation-free rule)
__device__ float g_lift[NPTS * KNB * CMID];   // 64 MB
__device__ float g_ploc[NPTS * 64];           // padded pts_local rows (48->64)
__device__ float g_cvwT[64 * 256];            // padded transposed conv weights
__device__ float g_xa[NPTS * 256];
__device__ float g_xb[NPTS * 256];
__device__ float g_X [NPTS * 256];
__device__ float g_dw[NPTS * CDIM];           // 25 MB
__device__ float g_stats[2 * COUT];

// ---------------------------------------------------------------------------
__global__ void k_zero_stats() { g_stats[threadIdx.x] = 0.f; }

// ---------------------------------------------------------------------------
// Prep: build padded pts_local matrix [NPTS x 64] and padded conv weight [64 x 256].
__global__ __launch_bounds__(256) void k_prep(
    const float* __restrict__ pts, const float* __restrict__ rep,
    const float* __restrict__ cvw)
{
    int idx = blockIdx.x * 256 + threadIdx.x;
    if (idx < NPTS * 64) {
        int m = idx >> 6, j = idx & 63;
        float v = 0.f;
        if (j < 48) {
            int d = j >> 4, k = j & 15;
            v = pts[(m * 16 + k) * 3 + d] - rep[m * 3 + d];
        }
        g_ploc[idx] = v;
    } else {
        int t = idx - NPTS * 64;
        if (t < 64 * 256) {
            int j = t >> 8, o = t & 255;
            g_cvwT[t] = (j < 48) ? cvw[o * 48 + j] : 0.f;
        }
    }
}

// ---------------------------------------------------------------------------
// K1: lift MLP: rows = NPTS*KNB, 64 rows/block.
__global__ __launch_bounds__(256) void k_lift(
    const float* __restrict__ pts, const float* __restrict__ rep,
    const float* __restrict__ w1, const float* __restrict__ b1,
    const float* __restrict__ w2, const float* __restrict__ b2)
{
    __shared__ float s_w1[3 * 64], s_b1[64], s_w2[64 * 64], s_b2[64];
    __shared__ float s_ploc[64 * 3];
    __shared__ float s_h[64 * 65];

    int tid = threadIdx.x;
    if (tid < 192) s_w1[tid] = w1[tid];
    if (tid < 64) { s_b1[tid] = b1[tid]; s_b2[tid] = b2[tid]; }
    for (int i = tid; i < 4096; i += 256) s_w2[i] = w2[i];

    int row0 = blockIdx.x * 64;
    if (tid < 192) {
        int lr = tid / 3, d = tid - lr * 3;
        int gr = row0 + lr;
        s_ploc[tid] = pts[gr * 3 + d] - rep[(gr >> 4) * 3 + d];
    }
    __syncthreads();

    #pragma unroll
    for (int it = 0; it < 16; it++) {
        int idx = tid + it * 256;
        int lr = idx >> 6, m = idx & 63;
        float a = s_b1[m];
        a = fmaf(s_ploc[lr * 3 + 0], s_w1[m],       a);
        a = fmaf(s_ploc[lr * 3 + 1], s_w1[64 + m],  a);
        a = fmaf(s_ploc[lr * 3 + 2], s_w1[128 + m], a);
        s_h[lr * 65 + m] = fmaxf(a, 0.f);
    }
    __syncthreads();

    int rg = tid >> 4, cg = tid & 15;
    int r0 = rg * 4, c0 = cg * 4;
    float acc[4][4];
    #pragma unroll
    for (int i = 0; i < 4; i++)
        #pragma unroll
        for (int jj = 0; jj < 4; jj++) acc[i][jj] = s_b2[c0 + jj];

    #pragma unroll 8
    for (int j = 0; j < 64; j++) {
        float4 w = *(const float4*)&s_w2[j * 64 + c0];
        #pragma unroll
        for (int i = 0; i < 4; i++) {
            float h = s_h[(r0 + i) * 65 + j];
            acc[i][0] = fmaf(h, w.x, acc[i][0]);
            acc[i][1] = fmaf(h, w.y, acc[i][1]);
            acc[i][2] = fmaf(h, w.z, acc[i][2]);
            acc[i][3] = fmaf(h, w.w, acc[i][3]);
        }
    }
    #pragma unroll
    for (int i = 0; i < 4; i++) {
        int gr = row0 + r0 + i;
        float4 v;
        v.x = fmaxf(acc[i][0], 0.f); v.y = fmaxf(acc[i][1], 0.f);
        v.z = fmaxf(acc[i][2], 0.f); v.w = fmaxf(acc[i][3], 0.f);
        *(float4*)&g_lift[gr * 64 + c0] = v;
    }
}

// ---------------------------------------------------------------------------
// Generic tiled FP32 GEMM: C[M x 256] = A[M x KDIM] @ B (+bias)(relu)(stats).
// Block: 64 M-rows x 256 N-cols, 256 threads, 8x8 register tiles, K chunks of 32.
// BT=false: B is [KDIM x 256] row-major.  BT=true: B is [256 x KDIM] (transposed load).
template<int KDIM, bool BT, bool BIAS, bool RELU, bool STATS>
__global__ __launch_bounds__(256) void k_gemm(
    const float* __restrict__ A, const float* __restrict__ B,
    const float* __restrict__ bias, float* __restrict__ C)
{
    __shared__ float sA[32 * SA];
    __shared__ float sB[32 * SB];
    __shared__ float s_sum[256], s_ssq[256];

    int tid = threadIdx.x;
    int m0b = blockIdx.x * 64;
    int tm = tid >> 5, tn = tid & 31;
    int m0 = tm * 8, n0 = tn * 8;

    if (STATS) { s_sum[tid] = 0.f; s_ssq[tid] = 0.f; }

    float acc[8][8];
    if (BIAS) {
        float bb[8];
        *(float4*)&bb[0] = *(const float4*)&bias[n0];
        *(float4*)&bb[4] = *(const float4*)&bias[n0 + 4];
        #pragma unroll
        for (int i = 0; i < 8; i++)
            #pragma unroll
            for (int j = 0; j < 8; j++) acc[i][j] = bb[j];
    } else {
        #pragma unroll
        for (int i = 0; i < 8; i++)
            #pragma unroll
            for (int j = 0; j < 8; j++) acc[i][j] = 0.f;
    }

    for (int kt = 0; kt < KDIM; kt += 32) {
        __syncthreads();
        // stage A: 64 x 32 (transposed: sA[kk][m]) — 512 float4s, 2 per thread
        #pragma unroll
        for (int i = 0; i < 2; i++) {
            int idx = tid + i * 256;
            int m = idx >> 3, kq = idx & 7;
            float4 v = *(const float4*)&A[(m0b + m) * KDIM + kt + kq * 4];
            sA[(kq * 4 + 0) * SA + m] = v.x;
            sA[(kq * 4 + 1) * SA + m] = v.y;
            sA[(kq * 4 + 2) * SA + m] = v.z;
            sA[(kq * 4 + 3) * SA + m] = v.w;
        }
        // stage B: 32 x 256 (sB[kk][o])
        if (BT) {
            #pragma unroll
            for (int i = 0; i < 8; i++) {
                int idx = tid + i * 256;
                int o = idx >> 3, kq = idx & 7;
                float4 v = *(const float4*)&B[o * KDIM + kt + kq * 4];
                sB[(kq * 4 + 0) * SB + o] = v.x;
                sB[(kq * 4 + 1) * SB + o] = v.y;
                sB[(kq * 4 + 2) * SB + o] = v.z;
                sB[(kq * 4 + 3) * SB + o] = v.w;
            }
        } else {
            #pragma unroll
            for (int i = 0; i < 8; i++) {
                int idx = tid + i * 256;
                int kk = idx >> 6, oq = idx & 63;
                float4 v = *(const float4*)&B[(kt + kk) * 256 + oq * 4];
                *(float4*)&sB[kk * SB + oq * 4] = v;
            }
        }
        __syncthreads();

        #pragma unroll 8
        for (int kk = 0; kk < 32; kk++) {
            float a[8], b[8];
            *(float4*)&a[0] = *(const float4*)&sA[kk * SA + m0];
            *(float4*)&a[4] = *(const float4*)&sA[kk * SA + m0 + 4];
            *(float4*)&b[0] = *(const float4*)&sB[kk * SB + n0];
            *(float4*)&b[4] = *(const float4*)&sB[kk * SB + n0 + 4];
            #pragma unroll
            for (int i = 0; i < 8; i++)
                #pragma unroll
                for (int j = 0; j < 8; j++)
                    acc[i][j] = fmaf(a[i], b[j], acc[i][j]);
        }
    }

    // epilogue
    float colsum[8], colssq[8];
    if (STATS)
        #pragma unroll
        for (int j = 0; j < 8; j++) { colsum[j] = 0.f; colssq[j] = 0.f; }

    #pragma unroll
    for (int i = 0; i < 8; i++) {
        float v[8];
        #pragma unroll
        for (int j = 0; j < 8; j++) {
            v[j] = RELU ? fmaxf(acc[i][j], 0.f) : acc[i][j];
            if (STATS) { colsum[j] += v[j]; colssq[j] += v[j] * v[j]; }
        }
        float* crow = &C[(m0b + m0 + i) * 256 + n0];
        *(float4*)&crow[0] = *(float4*)&v[0];
        *(float4*)&crow[4] = *(float4*)&v[4];
    }

    if (STATS) {
        #pragma unroll
        for (int j = 0; j < 8; j++) {
            atomicAdd(&s_sum[n0 + j], colsum[j]);
            atomicAdd(&s_ssq[n0 + j], colssq[j]);
        }
        __syncthreads();
        atomicAdd(&g_stats[tid],        s_sum[tid]);
        atomicAdd(&g_stats[COUT + tid], s_ssq[tid]);
    }
}

// ---------------------------------------------------------------------------
// k_mix: per point, fts_X = X @ cat and depthwise conv, register-resident.
// 2 points per block, 384 threads: thread = one channel column c of one point.
__global__ __launch_bounds__(384) void k_mix(
    const float* __restrict__ fts, const float* __restrict__ dww,
    const float* __restrict__ dwb)
{
    __shared__ float s_X[2 * 256];
    __shared__ float s_dw3[16 * 384];   // [k][m*192 + c]  conflict-free reads
    __shared__ float s_db[384];

    int tid = threadIdx.x;
    int p0 = blockIdx.x * 2;

    for (int i = tid; i < 512; i += 384) s_X[i] = g_X[p0 * 256 + i];
    for (int i = tid; i < 6144; i += 384) {
        int k = i & 15, cm = i >> 4, m = cm & 1, c = cm >> 1;
        s_dw3[k * 384 + m * 192 + c] = dww[i];
    }
    s_db[tid] = dwb[tid];
    __syncthreads();

    int p = tid / 192, c = tid % 192;
    int gp = p0 + p;

    float cat[16];
    #pragma unroll
    for (int j = 0; j < 16; j++)
        cat[j] = (c < 64) ? g_lift[(gp * 16 + j) * 64 + c]
                          : fts[(gp * 16 + j) * 128 + (c - 64)];

    const float* Xp = &s_X[p * 256];
    float fx[16];
    #pragma unroll
    for (int k = 0; k < 16; k++) {
        float4 x0 = *(const float4*)&Xp[k * 16];
        float4 x1 = *(const float4*)&Xp[k * 16 + 4];
        float4 x2 = *(const float4*)&Xp[k * 16 + 8];
        float4 x3 = *(const float4*)&Xp[k * 16 + 12];
        float a;
        a = x0.x * cat[0];
        a = fmaf(x0.y, cat[1], a);  a = fmaf(x0.z, cat[2], a);  a = fmaf(x0.w, cat[3], a);
        a = fmaf(x1.x, cat[4], a);  a = fmaf(x1.y, cat[5], a);  a = fmaf(x1.z, cat[6], a);
        a = fmaf(x1.w, cat[7], a);  a = fmaf(x2.x, cat[8], a);  a = fmaf(x2.y, cat[9], a);
        a = fmaf(x2.z, cat[10], a); a = fmaf(x2.w, cat[11], a); a = fmaf(x3.x, cat[12], a);
        a = fmaf(x3.y, cat[13], a); a = fmaf(x3.z, cat[14], a); a = fmaf(x3.w, cat[15], a);
        fx[k] = a;
    }

    float d0 = s_db[c * 2], d1 = s_db[c * 2 + 1];
    #pragma unroll
    for (int k = 0; k < 16; k++) {
        d0 = fmaf(fx[k], s_dw3[k * 384 + c],       d0);
        d1 = fmaf(fx[k], s_dw3[k * 384 + 192 + c], d1);
    }
    *(float2*)&g_dw[gp * 384 + c * 2] = make_float2(d0, d1);
}

// ---------------------------------------------------------------------------
// BN normalize in place.
__global__ __launch_bounds__(256) void k_bn(
    float* __restrict__ out, const float* __restrict__ g, const float* __restrict__ b)
{
    int idx = blockIdx.x * 256 + threadIdx.x;
    int o = idx & 255;
    float mean = g_stats[o] * (1.0f / 16384.0f);
    float var  = g_stats[COUT + o] * (1.0f / 16384.0f) - mean * mean;
    float sc = rsqrtf(var + 1e-5f) * g[o];
    out[idx] = (out[idx] - mean) * sc + b[o];
}

// ---------------------------------------------------------------------------
extern "C" void kernel_launch(void* const* d_in, const int* in_sizes, int n_in,
                              void* d_out, int out_size)
{
    const float* rep = (const float*)d_in[0];
    const float* pts = (const float*)d_in[1];
    const float* fts = (const float*)d_in[2];
    const float* d1w = (const float*)d_in[3];
    const float* d1b = (const float*)d_in[4];
    const float* d2w = (const float*)d_in[5];
    const float* d2b = (const float*)d_in[6];
    const float* cvw = (const float*)d_in[7];
    const float* cvb = (const float*)d_in[8];
    const float* x1w = (const float*)d_in[9];
    const float* x1b = (const float*)d_in[10];
    const float* x2w = (const float*)d_in[11];
    const float* x2b = (const float*)d_in[12];
    const float* dww = (const float*)d_in[13];
    const float* dwb = (const float*)d_in[14];
    const float* pww = (const float*)d_in[15];
    const float* bng = (const float*)d_in[16];
    const float* bnb = (const float*)d_in[17];
    float* out = (float*)d_out;

    float* ploc; cudaGetSymbolAddress((void**)&ploc, g_ploc);
    float* cvwT; cudaGetSymbolAddress((void**)&cvwT, g_cvwT);
    float* xa;   cudaGetSymbolAddress((void**)&xa,   g_xa);
    float* xb;   cudaGetSymbolAddress((void**)&xb,   g_xb);
    float* Xm;   cudaGetSymbolAddress((void**)&Xm,   g_X);
    float* dwp;  cudaGetSymbolAddress((void**)&dwp,  g_dw);

    k_zero_stats<<<1, 512>>>();
    k_prep<<<(NPTS * 64 + 64 * 256 + 255) / 256, 256>>>(pts, rep, cvw);
    k_lift<<<4096, 256>>>(pts, rep, d1w, d1b, d2w, d2b);
    // conv stage: [NPTS x 64(pad)] @ [64 x 256] + cvb, relu
    k_gemm<64,  false, true,  true,  false><<<256, 256>>>(ploc, cvwT, cvb, xa);
    // x1: relu
    k_gemm<256, false, true,  true,  false><<<256, 256>>>(xa, x1w, x1b, xb);
    // x2: no relu
    k_gemm<256, false, true,  false, false><<<256, 256>>>(xb, x2w, x2b, Xm);
    // per-point transform + depthwise
    k_mix<<<NPTS / 2, 384>>>(fts, dww, dwb);
    // pointwise (B transposed) + relu + BN stats
    k_gemm<384, true,  false, true,  true ><<<256, 256>>>(dwp, pww, nullptr, out);
    k_bn<<<16384, 256>>>(out, bng, bnb);
}